// round 2
// baseline (speedup 1.0000x reference)
#include <cuda_runtime.h>
#include <cstdint>

#define NN 6400
#define CC 64
#define HH 80

// Precomputed tables for Ad: E[d] = exp(-d^2/2), S1[r] = sum_{r'} E[|r-r'|]
__device__ float d_E[HH];
__device__ float d_S1[HH];

// ---------------------------------------------------------------------------
// k0: build the 80-entry tables (trivial)
// ---------------------------------------------------------------------------
__global__ void k0_tables() {
    __shared__ float sE[HH];
    int t = threadIdx.x;
    if (t < HH) {
        float e = __expf(-0.5f * (float)(t * t));
        sE[t] = e;
        d_E[t] = e;
    }
    __syncthreads();
    if (t < HH) {
        float s = 0.0f;
        #pragma unroll 8
        for (int r = 0; r < HH; r++) {
            int d = t - r;
            d = d < 0 ? -d : d;
            s += sE[d];
        }
        d_S1[t] = s;
    }
}

// ---------------------------------------------------------------------------
// k3: Ad — pure analytic, STG-bound. One float4 per thread.
// Ad[i][j] = E[|ri-rj|]*E[|ci-cj|] / (S1[ri]*S1[ci]-1), diag = 0.
// ---------------------------------------------------------------------------
__global__ __launch_bounds__(256) void k3_ad(float* __restrict__ Ad) {
    __shared__ float sE[HH];
    __shared__ float sS1[HH];
    int tid = threadIdx.x;
    if (tid < HH) {
        sE[tid]  = d_E[tid];
        sS1[tid] = d_S1[tid];
    }
    __syncthreads();

    size_t q = (size_t)blockIdx.x * 256 + tid;   // float4 index
    size_t e = q * 4;                            // element index
    int i  = (int)(e / NN);
    int j0 = (int)(e - (size_t)i * NN);          // j0 % 4 == 0, j0..j0+3 share rj
    int ri = i / HH,  ci = i - ri * HH;
    int rj = j0 / HH, cj = j0 - rj * HH;

    int dr = ri - rj; dr = dr < 0 ? -dr : dr;
    float inv  = 1.0f / (sS1[ri] * sS1[ci] - 1.0f);
    float base = sE[dr] * inv;

    float4 o;
    {
        int d0 = ci - cj;       d0 = d0 < 0 ? -d0 : d0;
        int d1 = ci - (cj + 1); d1 = d1 < 0 ? -d1 : d1;
        int d2 = ci - (cj + 2); d2 = d2 < 0 ? -d2 : d2;
        int d3 = ci - (cj + 3); d3 = d3 < 0 ? -d3 : d3;
        o.x = base * sE[d0];
        o.y = base * sE[d1];
        o.z = base * sE[d2];
        o.w = base * sE[d3];
    }
    // zero diagonal
    if (i == j0    ) o.x = 0.0f;
    if (i == j0 + 1) o.y = 0.0f;
    if (i == j0 + 2) o.z = 0.0f;
    if (i == j0 + 3) o.w = 0.0f;

    reinterpret_cast<float4*>(Ad)[q] = o;
}

// ---------------------------------------------------------------------------
// k1: fp32 GEMM  S = X @ X^T  (raw logits), written into the As output region.
// CTA tile 32 rows x 128 cols, 256 threads, 4x4 micro-tile.
// Warp layout: rt = warp id (rows rt*4..rt*4+3), ct = lane (cols ct*4..ct*4+3)
// -> A-fragment LDS is a warp-uniform broadcast (cheap), B-fragment LDS.128 is
//    conflict-free (consecutive lanes -> consecutive 16B).
// ---------------------------------------------------------------------------
__global__ __launch_bounds__(256) void k1_gemm(const float* __restrict__ X,
                                              float* __restrict__ S) {
    __shared__ float sA[CC * 32];    // transposed: sA[k*32 + r]
    __shared__ float sB[CC * 128];   // transposed: sB[k*128 + c]

    const int tid = threadIdx.x;
    const int r0 = blockIdx.y * 32;
    const int c0 = blockIdx.x * 128;

    // ---- load A tile (32 rows x 64) transposed ----
    {
        int ar = tid & 31;           // row within tile
        int kq = tid >> 5;           // 0..7 -> k base kq*8
        const float4* src =
            reinterpret_cast<const float4*>(X + (size_t)(r0 + ar) * CC) + kq * 2;
        float4 v0 = src[0];
        float4 v1 = src[1];
        int kb = kq * 8;
        sA[(kb + 0) * 32 + ar] = v0.x;
        sA[(kb + 1) * 32 + ar] = v0.y;
        sA[(kb + 2) * 32 + ar] = v0.z;
        sA[(kb + 3) * 32 + ar] = v0.w;
        sA[(kb + 4) * 32 + ar] = v1.x;
        sA[(kb + 5) * 32 + ar] = v1.y;
        sA[(kb + 6) * 32 + ar] = v1.z;
        sA[(kb + 7) * 32 + ar] = v1.w;
    }
    // ---- load B tile (128 cols x 64) transposed ----
    {
        int bc = tid & 127;          // col within tile
        int h  = tid >> 7;           // 0..1 -> k half h*32
        const float4* src =
            reinterpret_cast<const float4*>(X + (size_t)(c0 + bc) * CC + h * 32);
        #pragma unroll
        for (int q = 0; q < 8; q++) {
            float4 v = src[q];
            int k = h * 32 + q * 4;
            sB[(k + 0) * 128 + bc] = v.x;
            sB[(k + 1) * 128 + bc] = v.y;
            sB[(k + 2) * 128 + bc] = v.z;
            sB[(k + 3) * 128 + bc] = v.w;
        }
    }
    __syncthreads();

    const int rt = tid >> 5;   // warp id: rows rt*4..+3
    const int ct = tid & 31;   // lane:    cols ct*4..+3

    float acc[4][4];
    #pragma unroll
    for (int i = 0; i < 4; i++)
        #pragma unroll
        for (int j = 0; j < 4; j++)
            acc[i][j] = 0.0f;

    #pragma unroll
    for (int k = 0; k < CC; k++) {
        float4 a = *reinterpret_cast<const float4*>(&sA[k * 32 + rt * 4]);
        float4 b = *reinterpret_cast<const float4*>(&sB[k * 128 + ct * 4]);
        acc[0][0] += a.x * b.x; acc[0][1] += a.x * b.y;
        acc[0][2] += a.x * b.z; acc[0][3] += a.x * b.w;
        acc[1][0] += a.y * b.x; acc[1][1] += a.y * b.y;
        acc[1][2] += a.y * b.z; acc[1][3] += a.y * b.w;
        acc[2][0] += a.z * b.x; acc[2][1] += a.z * b.y;
        acc[2][2] += a.z * b.z; acc[2][3] += a.z * b.w;
        acc[3][0] += a.w * b.x; acc[3][1] += a.w * b.y;
        acc[3][2] += a.w * b.z; acc[3][3] += a.w * b.w;
    }

    float* out = S + (size_t)(r0 + rt * 4) * NN + (c0 + ct * 4);
    #pragma unroll
    for (int i = 0; i < 4; i++) {
        float4 v = make_float4(acc[i][0], acc[i][1], acc[i][2], acc[i][3]);
        *reinterpret_cast<float4*>(out + (size_t)i * NN) = v;
    }
}

// ---------------------------------------------------------------------------
// k2: per-row softmax finalize (in place on the raw logits).
// One row per CTA. mean(softmax_row) == 1/N exactly, so threshold = 1/N.
// ---------------------------------------------------------------------------
__global__ __launch_bounds__(256) void k2_softmax(float* __restrict__ S) {
    __shared__ float4 sbuf[NN / 4];   // 25.6 KB row cache
    __shared__ float  sred[8];

    const int tid = threadIdx.x;
    const int row = blockIdx.x;
    float4* rowp = reinterpret_cast<float4*>(S + (size_t)row * NN);

    // load row + local max
    float lmax = -3.0e38f;
    for (int i = tid; i < NN / 4; i += 256) {
        float4 v = rowp[i];
        sbuf[i] = v;
        lmax = fmaxf(lmax, fmaxf(fmaxf(v.x, v.y), fmaxf(v.z, v.w)));
    }
    #pragma unroll
    for (int o = 16; o; o >>= 1)
        lmax = fmaxf(lmax, __shfl_xor_sync(0xFFFFFFFFu, lmax, o));
    if ((tid & 31) == 0) sred[tid >> 5] = lmax;
    __syncthreads();
    float m = sred[0];
    #pragma unroll
    for (int w = 1; w < 8; w++) m = fmaxf(m, sred[w]);
    __syncthreads();   // all reads of sred done before reuse

    // sum of exp(s - m)
    float lsum = 0.0f;
    for (int i = tid; i < NN / 4; i += 256) {
        float4 v = sbuf[i];
        lsum += __expf(v.x - m) + __expf(v.y - m) +
                __expf(v.z - m) + __expf(v.w - m);
    }
    #pragma unroll
    for (int o = 16; o; o >>= 1)
        lsum += __shfl_xor_sync(0xFFFFFFFFu, lsum, o);
    if ((tid & 31) == 0) sred[tid >> 5] = lsum;
    __syncthreads();
    float Z = 0.0f;
    #pragma unroll
    for (int w = 0; w < 8; w++) Z += sred[w];

    const float invZ = 1.0f / Z;
    const float avg  = 1.0f / (float)NN;

    for (int i = tid; i < NN / 4; i += 256) {
        float4 v = sbuf[i];
        float4 o;
        float px = __expf(v.x - m) * invZ;
        float py = __expf(v.y - m) * invZ;
        float pz = __expf(v.z - m) * invZ;
        float pw = __expf(v.w - m) * invZ;
        o.x = (px < avg) ? 0.0f : px;
        o.y = (py < avg) ? 0.0f : py;
        o.z = (pz < avg) ? 0.0f : pz;
        o.w = (pw < avg) ? 0.0f : pw;
        rowp[i] = o;
    }
}

// ---------------------------------------------------------------------------
extern "C" void kernel_launch(void* const* d_in, const int* in_sizes, int n_in,
                              void* d_out, int out_size) {
    const float* X = (const float*)d_in[0];
    float* Ad = (float*)d_out;                       // first N*N floats
    float* As = (float*)d_out + (size_t)NN * NN;     // second N*N floats

    k0_tables<<<1, 128>>>();
    k3_ad<<<(NN * (NN / 4)) / 256, 256>>>(Ad);       // 40000 blocks
    k1_gemm<<<dim3(NN / 128, NN / 32), 256>>>(X, As); // 50 x 200 blocks
    k2_softmax<<<NN, 256>>>(As);
}